// round 15
// baseline (speedup 1.0000x reference)
#include <cuda_runtime.h>
#include <cuda_fp16.h>
#include <math.h>
#include <float.h>
#include <stdint.h>

#define FS        16000.0f
#define N_FILT    80
#define FILT_DIM  251
#define HALF_K    125
#define L_IN      32000
#define L_OUT     (L_IN - FILT_DIM + 1)   // 31750
#define BATCH     32

#define KF        128
#define KSTEPS    8
#define NT        10
#define MTILE     128
#define NLT       ((L_OUT + MTILE - 1) / MTILE)   // 249
#define THREADS   256

// bank-stagger offsets (floats): word(XF1)-word(XF0) = 272 = 0 mod 16 is bad;
// 272 words -> float2 index offset 136 = 8 mod 16 -> parity windows disjoint.
#define XF0       0
#define XF1       272
#define XR0       544
#define XR1       816
#define XBUF_LEN  1088

// Folded H (fp16, unsplit): [kstep][ntile][lane] -> uint2 {b0, b1}
// b0 = (H'[f][16ks+2q], H'[f][16ks+2q+1]), b1 = same k+8; f = 8*nt + (lane>>2)
__device__ __align__(16) uint2 Hfrag_g[KSTEPS][NT][32];

struct Smem { float xbuf[XBUF_LEN]; };

// ---------------------------------------------------------------------------
__device__ __forceinline__ void mma16816(float d[4],
                                         uint32_t a0, uint32_t a1,
                                         uint32_t a2, uint32_t a3,
                                         uint32_t b0, uint32_t b1) {
    asm volatile(
        "mma.sync.aligned.m16n8k16.row.col.f32.f16.f16.f32 "
        "{%0,%1,%2,%3}, {%4,%5,%6,%7}, {%8,%9}, {%0,%1,%2,%3};"
        : "+f"(d[0]), "+f"(d[1]), "+f"(d[2]), "+f"(d[3])
        : "r"(a0), "r"(a1), "r"(a2), "r"(a3), "r"(b0), "r"(b1));
}

// s-pair -> (hi f16x2, lo f16x2). lo captures the fp16 remainder of s.
__device__ __forceinline__ void mk_frag(uint32_t& hi, uint32_t& lo,
                                        float2 a, float2 b) {
    float sx = a.x + b.x;
    float sy = a.y + b.y;
    __half2 h2 = __float22half2_rn(make_float2(sx, sy));   // .x -> low 16 bits
    float2 hf = __half22float2(h2);
    __half2 l2 = __float22half2_rn(make_float2(sx - hf.x, sy - hf.y));
    hi = *(uint32_t*)&h2;
    lo = *(uint32_t*)&l2;
}

// ---------------------------------------------------------------------------
// Kernel 1: build FOLDED taps (reference numerics; averaged window pair),
// cast to fp16 (no split), packed fragment-linear.
// H'[125] = center/2 because the uniform pair formula gives s(125) = 2x.
// ---------------------------------------------------------------------------
__global__ void build_filters_kernel(const float* __restrict__ norm_f1,
                                     const float* __restrict__ norm_f2,
                                     const float* __restrict__ amplitude)
{
    const int f = blockIdx.x;
    const int t = threadIdx.x;

    const float min_n = 50.0f / FS;
    float f1n = fabsf(norm_f1[f]) + min_n;
    float f2n = f1n + fabsf(norm_f2[f] - f1n) + min_n;
    float f1 = f1n * FS;
    float f2 = f2n * FS;
    float amp = fabsf(amplitude[f]);

    __shared__ float bp[HALF_K];
    __shared__ float red[128];

    const float TWO_PI = 6.283185307179586f;

    float v = -FLT_MAX;
    if (t < HALF_K) {
        float tr = (float)(t + 1) / FS;          // exact integers 1..125 / fs
        float a2 = TWO_PI * f2 * tr;             // fp32 arg like reference
        float a1 = TWO_PI * f1 * tr;
        float s2 = (float)(sin((double)a2) / (double)a2);
        float s1 = (float)(sin((double)a1) / (double)a1);
        float bb = amp * (2.0f * f2 * s2 - 2.0f * f1 * s1);
        bp[t] = bb;
        v = bb;
    }
    float center = amp * (2.0f * f2 - 2.0f * f1);
    v = fmaxf(v, center);

    red[t] = v;
    __syncthreads();
    for (int s = 64; s > 0; s >>= 1) {
        if (t < s) red[t] = fmaxf(red[t], red[t + s]);
        __syncthreads();
    }
    float mx = red[0];

    const int nt   = f >> 3;
    const int lrow = f & 7;

    for (int k = t; k < KF; k += blockDim.x) {
        float hv = 0.0f;
        if (k < HALF_K) {
            double wj  = 0.54 - 0.46 * cos(2.0 * M_PI * (double)k / 250.0);
            double wjm = 0.54 - 0.46 * cos(2.0 * M_PI * (double)(250 - k) / 250.0);
            hv = (bp[HALF_K - 1 - k] / mx) * (float)(0.5 * (wj + wjm));
        } else if (k == HALF_K) {
            hv = 0.5f * (center / mx);           // s(125) = 2x -> halve tap
        }
        __half hh = __float2half_rn(hv);

        int ks = k >> 4, kk = k & 15;
        int bsel = kk >> 3;
        int q    = (kk >> 1) & 3;
        int e    = kk & 1;
        int lane = lrow * 4 + q;

        __half* dst = (__half*)&Hfrag_g[ks][nt][lane];
        dst[bsel * 2 + e] = hh;     // uint2 = 4 halves: b0.lo,b0.hi,b1.lo,b1.hi
    }
}

// ---------------------------------------------------------------------------
// Kernel 2: folded implicit-GEMM via mma.sync m16n8k16 fp16 (2-pass x-split),
// sliding-window register carry: full kstep unroll, windows advance +8 f2
// words per kstep so 3/5 of each side's loads become register renames
// (LDS.64 per warp-kstep: 10 -> 4).
// CTA: 1 batch x 128 l x 80 f, 8 warps. Warp w = (mp = w&3, nh = w>>2).
// ---------------------------------------------------------------------------
__global__ void __launch_bounds__(THREADS, 2)
sinc_conv_kernel(const float* __restrict__ x, float* __restrict__ out)
{
    extern __shared__ __align__(16) Smem S[];
    float* xbuf = S->xbuf;

    const int b    = blockIdx.y;
    const int l0   = blockIdx.x * MTILE;
    const int tid  = threadIdx.x;
    const int w    = tid >> 5;
    const int lane = tid & 31;

    // ---- stage forward + reversed (and +1 shifted) x copies, clamped ----
    {
        const float* xb = x + (size_t)b * L_IN;
        for (int i = tid; i < 256; i += THREADS) {
            int gf = l0 + i;
            xbuf[XF0 + i] = (gf < L_IN) ? xb[gf] : 0.0f;
            xbuf[XF1 + i] = (gf + 1 < L_IN) ? xb[gf + 1] : 0.0f;
            int gr = l0 + 377 - i;
            xbuf[XR0 + i] = (gr < L_IN) ? xb[gr] : 0.0f;
            int g2 = l0 + 376 - i;
            xbuf[XR1 + i] = (g2 < L_IN) ? xb[g2] : 0.0f;
        }
    }
    __syncthreads();

    const int mp  = w & 3;
    const int nh  = w >> 2;
    const int gid = lane >> 2;
    const int tig = lane & 3;
    const int par = gid & 1;        // parity of r (16*mt even)
    const int qq  = 1 - par;        // parity of rev index

    const int rA  = 32 * mp + gid;  // row of m-tile 2mp for this lane

    const float2* Xf = (const float2*)(xbuf + (par ? XF1 : XF0));
    const float2* Xr = (const float2*)(xbuf + (qq ? XR1 : XR0));

    const int vb0 = (rA - par + 2 * tig) >> 1;            // fwd base, ks=0
    const int ub0 = (127 - rA + 2 * tig - 24 - qq) >> 1;  // rev base, ks=0

    float D[2][5][4];
    #pragma unroll
    for (int m = 0; m < 2; m++)
        #pragma unroll
        for (int n = 0; n < 5; n++)
            #pragma unroll
            for (int e = 0; e < 4; e++)
                D[m][n][e] = 0.0f;

    // prologue window loads
    float2 F0 = Xf[vb0],      F1 = Xf[vb0 + 4],  F2 = Xf[vb0 + 8];
    float2 F3 = Xf[vb0 + 12], F4 = Xf[vb0 + 16];
    float2 R0 = Xr[ub0],      R1 = Xr[ub0 + 4],  R2 = Xr[ub0 + 8];
    float2 R3 = Xr[ub0 + 12], R4 = Xr[ub0 + 16];

    #pragma unroll
    for (int ks = 0; ks < KSTEPS; ks++) {
        uint4 Ah0, Al0, Ah1, Al1;
        mk_frag(Ah0.x, Al0.x, F0, R3);   // (r,    k0)
        mk_frag(Ah0.y, Al0.y, F1, R2);   // (r+8,  k0)
        mk_frag(Ah0.z, Al0.z, F1, R4);   // (r,    k0+8)
        mk_frag(Ah0.w, Al0.w, F2, R3);   // (r+8,  k0+8)
        mk_frag(Ah1.x, Al1.x, F2, R1);   // (r+16, k0)
        mk_frag(Ah1.y, Al1.y, F3, R0);   // (r+24, k0)
        mk_frag(Ah1.z, Al1.z, F3, R2);   // (r+16, k0+8)
        mk_frag(Ah1.w, Al1.w, F4, R1);   // (r+24, k0+8)

        const uint2* __restrict__ Hp = &Hfrag_g[ks][5 * nh][lane];
        #pragma unroll
        for (int n = 0; n < 5; n++) {
            uint2 Bf = Hp[n * 32];          // LDG.64, L1/L2-hot
            mma16816(D[0][n], Ah0.x, Ah0.y, Ah0.z, Ah0.w, Bf.x, Bf.y);  // h*sh
            mma16816(D[0][n], Al0.x, Al0.y, Al0.z, Al0.w, Bf.x, Bf.y);  // h*sl
            mma16816(D[1][n], Ah1.x, Ah1.y, Ah1.z, Ah1.w, Bf.x, Bf.y);
            mma16816(D[1][n], Al1.x, Al1.y, Al1.z, Al1.w, Bf.x, Bf.y);
        }

        // slide windows by 8 f2-words (register renames + 4 fresh LDS.64)
        if (ks < KSTEPS - 1) {
            const int nb = 8 * (ks + 1);
            F0 = F2; F1 = F3; F2 = F4;
            F3 = Xf[vb0 + nb + 12];
            F4 = Xf[vb0 + nb + 16];
            R0 = R2; R1 = R3; R2 = R4;
            R3 = Xr[ub0 + nb + 12];
            R4 = Xr[ub0 + nb + 16];
        }
    }

    // ---- store (direct): m-tile (2mp+m): l = l0+16(2mp+m)+rp (+8) ----
    const int rp = lane >> 2;
    const int q  = lane & 3;
    float* ob = out + (size_t)b * N_FILT * L_OUT;
    #pragma unroll
    for (int m = 0; m < 2; m++) {
        const int l = l0 + 16 * (2 * mp + m) + rp;
        #pragma unroll
        for (int n = 0; n < 5; n++) {
            int f = (5 * nh + n) * 8 + q * 2;
            if (l < L_OUT) {
                ob[(size_t)f * L_OUT + l]       = D[m][n][0];
                ob[(size_t)(f + 1) * L_OUT + l] = D[m][n][1];
            }
            if (l + 8 < L_OUT) {
                ob[(size_t)f * L_OUT + l + 8]       = D[m][n][2];
                ob[(size_t)(f + 1) * L_OUT + l + 8] = D[m][n][3];
            }
        }
    }
}

// ---------------------------------------------------------------------------
extern "C" void kernel_launch(void* const* d_in, const int* in_sizes, int n_in,
                              void* d_out, int out_size)
{
    const float* x       = (const float*)d_in[0];
    const float* norm_f1 = (const float*)d_in[1];
    const float* norm_f2 = (const float*)d_in[2];
    const float* ampl    = (const float*)d_in[3];
    float* out = (float*)d_out;

    cudaFuncSetAttribute(sinc_conv_kernel,
                         cudaFuncAttributeMaxDynamicSharedMemorySize,
                         (int)sizeof(Smem));

    build_filters_kernel<<<N_FILT, 128>>>(norm_f1, norm_f2, ampl);

    dim3 grid(NLT, BATCH);   // (249, 32)
    sinc_conv_kernel<<<grid, THREADS, sizeof(Smem)>>>(x, out);
}

// round 16
// speedup vs baseline: 1.0927x; 1.0927x over previous
#include <cuda_runtime.h>
#include <cuda_fp16.h>
#include <math.h>
#include <float.h>
#include <stdint.h>

#define FS        16000.0f
#define N_FILT    80
#define FILT_DIM  251
#define HALF_K    125
#define L_IN      32000
#define L_OUT     (L_IN - FILT_DIM + 1)   // 31750
#define BATCH     32

#define KF        128
#define KSTEPS    8
#define NT        10
#define MTILE     64
#define NLT       ((L_OUT + MTILE - 1) / MTILE)   // 497
#define THREADS   256

// float strides between parity arrays: 464 mod 32 == 16 -> the two parity
// windows are disjoint mod 16 f2-banks (conflict-free LDS.64)
#define XF0       0
#define XF1       464
#define XR0       928
#define XR1       1392
#define XBUF_LEN  1856

// Folded H (fp16, unsplit): [kstep][ntile][lane] -> uint2 {b0, b1}
// b0 = (H'[f][16ks+2q], H'[f][16ks+2q+1]), b1 = same k+8; f = 8*nt + (lane>>2)
__device__ __align__(16) uint2 Hfrag_g[KSTEPS][NT][32];

struct Smem { float xbuf[XBUF_LEN]; };

// ---------------------------------------------------------------------------
__device__ __forceinline__ void mma16816(float d[4],
                                         uint32_t a0, uint32_t a1,
                                         uint32_t a2, uint32_t a3,
                                         uint32_t b0, uint32_t b1) {
    asm volatile(
        "mma.sync.aligned.m16n8k16.row.col.f32.f16.f16.f32 "
        "{%0,%1,%2,%3}, {%4,%5,%6,%7}, {%8,%9}, {%0,%1,%2,%3};"
        : "+f"(d[0]), "+f"(d[1]), "+f"(d[2]), "+f"(d[3])
        : "r"(a0), "r"(a1), "r"(a2), "r"(a3), "r"(b0), "r"(b1));
}

// s-pair -> (hi f16x2, lo f16x2). lo captures the fp16 remainder of s.
__device__ __forceinline__ void mk_frag(uint32_t& hi, uint32_t& lo,
                                        float2 a, float2 b) {
    float sx = a.x + b.x;
    float sy = a.y + b.y;
    __half2 h2 = __float22half2_rn(make_float2(sx, sy));   // .x -> low 16 bits
    float2 hf = __half22float2(h2);
    __half2 l2 = __float22half2_rn(make_float2(sx - hf.x, sy - hf.y));
    hi = *(uint32_t*)&h2;
    lo = *(uint32_t*)&l2;
}

// ---------------------------------------------------------------------------
// Kernel 1: build FOLDED taps (reference numerics; averaged window pair),
// cast to fp16 (no split), packed fragment-linear.
// H'[125] = center/2 because the uniform pair formula gives s(125) = 2x.
// ---------------------------------------------------------------------------
__global__ void build_filters_kernel(const float* __restrict__ norm_f1,
                                     const float* __restrict__ norm_f2,
                                     const float* __restrict__ amplitude)
{
    const int f = blockIdx.x;
    const int t = threadIdx.x;

    const float min_n = 50.0f / FS;
    float f1n = fabsf(norm_f1[f]) + min_n;
    float f2n = f1n + fabsf(norm_f2[f] - f1n) + min_n;
    float f1 = f1n * FS;
    float f2 = f2n * FS;
    float amp = fabsf(amplitude[f]);

    __shared__ float bp[HALF_K];
    __shared__ float red[128];

    const float TWO_PI = 6.283185307179586f;

    float v = -FLT_MAX;
    if (t < HALF_K) {
        float tr = (float)(t + 1) / FS;          // exact integers 1..125 / fs
        float a2 = TWO_PI * f2 * tr;             // fp32 arg like reference
        float a1 = TWO_PI * f1 * tr;
        float s2 = (float)(sin((double)a2) / (double)a2);
        float s1 = (float)(sin((double)a1) / (double)a1);
        float bb = amp * (2.0f * f2 * s2 - 2.0f * f1 * s1);
        bp[t] = bb;
        v = bb;
    }
    float center = amp * (2.0f * f2 - 2.0f * f1);
    v = fmaxf(v, center);

    red[t] = v;
    __syncthreads();
    for (int s = 64; s > 0; s >>= 1) {
        if (t < s) red[t] = fmaxf(red[t], red[t + s]);
        __syncthreads();
    }
    float mx = red[0];

    const int nt   = f >> 3;
    const int lrow = f & 7;

    for (int k = t; k < KF; k += blockDim.x) {
        float hv = 0.0f;
        if (k < HALF_K) {
            double wj  = 0.54 - 0.46 * cos(2.0 * M_PI * (double)k / 250.0);
            double wjm = 0.54 - 0.46 * cos(2.0 * M_PI * (double)(250 - k) / 250.0);
            hv = (bp[HALF_K - 1 - k] / mx) * (float)(0.5 * (wj + wjm));
        } else if (k == HALF_K) {
            hv = 0.5f * (center / mx);           // s(125) = 2x -> halve tap
        }
        __half hh = __float2half_rn(hv);

        int ks = k >> 4, kk = k & 15;
        int bsel = kk >> 3;
        int q    = (kk >> 1) & 3;
        int e    = kk & 1;
        int lane = lrow * 4 + q;

        __half* dst = (__half*)&Hfrag_g[ks][nt][lane];
        dst[bsel * 2 + e] = hh;     // uint2 = 4 halves: b0.lo,b0.hi,b1.lo,b1.hi
    }
}

// ---------------------------------------------------------------------------
// Kernel 2: folded implicit-GEMM via mma.sync m16n8k16 fp16 (2-pass x-split).
// CTA: 1 batch x 64 l x 80 f, 8 warps, 3 CTAs/SM (24 warps).
// Warp w = (mp = w&3, nh = w>>2): ONE m-tile mp, n-tiles [5nh, 5nh+5).
// Windows register-carried across the fully-unrolled kstep loop.
// Mirror: x[l0+r+250-k] = XR0[79 - r + k] with XR0[i] = x[l0+329-i].
// ---------------------------------------------------------------------------
__global__ void __launch_bounds__(THREADS, 3)
sinc_conv_kernel(const float* __restrict__ x, float* __restrict__ out)
{
    extern __shared__ __align__(16) Smem S[];
    float* xbuf = S->xbuf;

    const int b    = blockIdx.y;
    const int l0   = blockIdx.x * MTILE;
    const int tid  = threadIdx.x;
    const int w    = tid >> 5;
    const int lane = tid & 31;

    // ---- stage forward + reversed (and shifted) x copies, clamped ----
    {
        const float* xb = x + (size_t)b * L_IN;
        int i = tid;                       // window reads stay below 256
        int gf = l0 + i;
        xbuf[XF0 + i] = (gf < L_IN) ? xb[gf] : 0.0f;
        xbuf[XF1 + i] = (gf + 1 < L_IN) ? xb[gf + 1] : 0.0f;
        int gr = l0 + 329 - i;             // >= l0 + 74 >= 0
        xbuf[XR0 + i] = (gr < L_IN) ? xb[gr] : 0.0f;
        xbuf[XR1 + i] = (gr - 1 < L_IN) ? xb[gr - 1] : 0.0f;
    }
    __syncthreads();

    const int mp  = w & 3;
    const int nh  = w >> 2;
    const int gid = lane >> 2;      // 0..7
    const int tig = lane & 3;
    const int par = gid & 1;        // parity of r (16*mp even)
    const int qq  = 1 - par;        // parity of mirror index 79 - rA + k0

    const int rA  = 16 * mp + gid;  // row of this lane's m-tile

    const float2* Xf = (const float2*)(xbuf + (par ? XF1 : XF0));
    const float2* Xr = (const float2*)(xbuf + (qq ? XR1 : XR0));

    const int vb0 = (rA - par + 2 * tig) >> 1;        // fwd word, ks=0
    const int ub0 = (79 - rA + 2 * tig - qq) >> 1;    // rev word of (r, k0), ks=0

    float D[5][4];
    #pragma unroll
    for (int n = 0; n < 5; n++)
        #pragma unroll
        for (int e = 0; e < 4; e++)
            D[n][e] = 0.0f;

    // prologue window loads
    float2 F0 = Xf[vb0], F1 = Xf[vb0 + 4], F2 = Xf[vb0 + 8];
    float2 R0 = Xr[ub0 - 4], R1 = Xr[ub0], R2 = Xr[ub0 + 4];

    #pragma unroll
    for (int ks = 0; ks < KSTEPS; ks++) {
        uint4 Ah, Al;
        mk_frag(Ah.x, Al.x, F0, R1);   // (r,   k0)
        mk_frag(Ah.y, Al.y, F1, R0);   // (r+8, k0)
        mk_frag(Ah.z, Al.z, F1, R2);   // (r,   k0+8)
        mk_frag(Ah.w, Al.w, F2, R1);   // (r+8, k0+8)

        const uint2* __restrict__ Hp = &Hfrag_g[ks][5 * nh][lane];
        #pragma unroll
        for (int n = 0; n < 5; n++) {
            uint2 Bf = Hp[n * 32];          // LDG.64, L1/L2-hot
            mma16816(D[n], Ah.x, Ah.y, Ah.z, Ah.w, Bf.x, Bf.y);  // h*sh
            mma16816(D[n], Al.x, Al.y, Al.z, Al.w, Bf.x, Bf.y);  // h*sl
        }

        // slide windows by 8 f2-words (1 rename + 2 fresh LDS.64 per side)
        if (ks < KSTEPS - 1) {
            const int nb = 8 * (ks + 1);
            F0 = F2;
            F1 = Xf[vb0 + nb + 4];
            F2 = Xf[vb0 + nb + 8];
            R0 = R2;
            R1 = Xr[ub0 + nb];
            R2 = Xr[ub0 + nb + 4];
        }
    }

    // ---- store: l = l0 + 16*mp + rp (+8); f = 8(5nh+n) + 2q (+1) ----
    const int rp = lane >> 2;
    const int q  = lane & 3;
    const int l  = l0 + 16 * mp + rp;
    float* ob = out + (size_t)b * N_FILT * L_OUT;
    #pragma unroll
    for (int n = 0; n < 5; n++) {
        int f = (5 * nh + n) * 8 + q * 2;
        if (l < L_OUT) {
            ob[(size_t)f * L_OUT + l]       = D[n][0];
            ob[(size_t)(f + 1) * L_OUT + l] = D[n][1];
        }
        if (l + 8 < L_OUT) {
            ob[(size_t)f * L_OUT + l + 8]       = D[n][2];
            ob[(size_t)(f + 1) * L_OUT + l + 8] = D[n][3];
        }
    }
}

// ---------------------------------------------------------------------------
extern "C" void kernel_launch(void* const* d_in, const int* in_sizes, int n_in,
                              void* d_out, int out_size)
{
    const float* x       = (const float*)d_in[0];
    const float* norm_f1 = (const float*)d_in[1];
    const float* norm_f2 = (const float*)d_in[2];
    const float* ampl    = (const float*)d_in[3];
    float* out = (float*)d_out;

    cudaFuncSetAttribute(sinc_conv_kernel,
                         cudaFuncAttributeMaxDynamicSharedMemorySize,
                         (int)sizeof(Smem));

    build_filters_kernel<<<N_FILT, 128>>>(norm_f1, norm_f2, ampl);

    dim3 grid(NLT, BATCH);   // (497, 32)
    sinc_conv_kernel<<<grid, THREADS, sizeof(Smem)>>>(x, out);
}

// round 17
// speedup vs baseline: 1.2111x; 1.1083x over previous
#include <cuda_runtime.h>
#include <cuda_fp16.h>
#include <math.h>
#include <float.h>
#include <stdint.h>

#define FS        16000.0f
#define N_FILT    80
#define FILT_DIM  251
#define HALF_K    125
#define L_IN      32000
#define L_OUT     (L_IN - FILT_DIM + 1)   // 31750
#define BATCH     32

#define KF        128
#define KSTEPS    8
#define NT        10
#define MTILE     64
#define NLT       ((L_OUT + MTILE - 1) / MTILE)   // 497
#define THREADS   256

// float strides between parity arrays: 464 mod 32 == 16 -> the two parity
// windows are disjoint mod 16 f2-banks (conflict-free LDS.64)
#define XF0       0
#define XF1       464
#define XR0       928
#define XR1       1392
#define XBUF_LEN  1856

// Folded H (fp16, unsplit): [kstep][ntile][lane] -> uint2 {b0, b1}
// b0 = (H'[f][16ks+2q], H'[f][16ks+2q+1]), b1 = same k+8; f = 8*nt + (lane>>2)
__device__ __align__(16) uint2 Hfrag_g[KSTEPS][NT][32];

struct Smem { float xbuf[XBUF_LEN]; };

// ---------------------------------------------------------------------------
__device__ __forceinline__ void mma16816(float d[4],
                                         uint32_t a0, uint32_t a1,
                                         uint32_t a2, uint32_t a3,
                                         uint32_t b0, uint32_t b1) {
    asm volatile(
        "mma.sync.aligned.m16n8k16.row.col.f32.f16.f16.f32 "
        "{%0,%1,%2,%3}, {%4,%5,%6,%7}, {%8,%9}, {%0,%1,%2,%3};"
        : "+f"(d[0]), "+f"(d[1]), "+f"(d[2]), "+f"(d[3])
        : "r"(a0), "r"(a1), "r"(a2), "r"(a3), "r"(b0), "r"(b1));
}

// s-pair -> f16x2 (single precision pass; remainder dropped)
__device__ __forceinline__ uint32_t mk_frag_hi(float2 a, float2 b) {
    __half2 h2 = __float22half2_rn(make_float2(a.x + b.x, a.y + b.y));
    return *(uint32_t*)&h2;
}

// ---------------------------------------------------------------------------
// Kernel 1: build FOLDED taps (reference numerics; averaged window pair),
// cast to fp16 (no split), packed fragment-linear.
// H'[125] = center/2 because the uniform pair formula gives s(125) = 2x.
// ---------------------------------------------------------------------------
__global__ void build_filters_kernel(const float* __restrict__ norm_f1,
                                     const float* __restrict__ norm_f2,
                                     const float* __restrict__ amplitude)
{
    const int f = blockIdx.x;
    const int t = threadIdx.x;

    const float min_n = 50.0f / FS;
    float f1n = fabsf(norm_f1[f]) + min_n;
    float f2n = f1n + fabsf(norm_f2[f] - f1n) + min_n;
    float f1 = f1n * FS;
    float f2 = f2n * FS;
    float amp = fabsf(amplitude[f]);

    __shared__ float bp[HALF_K];
    __shared__ float red[128];

    const float TWO_PI = 6.283185307179586f;

    float v = -FLT_MAX;
    if (t < HALF_K) {
        float tr = (float)(t + 1) / FS;          // exact integers 1..125 / fs
        float a2 = TWO_PI * f2 * tr;             // fp32 arg like reference
        float a1 = TWO_PI * f1 * tr;
        float s2 = (float)(sin((double)a2) / (double)a2);
        float s1 = (float)(sin((double)a1) / (double)a1);
        float bb = amp * (2.0f * f2 * s2 - 2.0f * f1 * s1);
        bp[t] = bb;
        v = bb;
    }
    float center = amp * (2.0f * f2 - 2.0f * f1);
    v = fmaxf(v, center);

    red[t] = v;
    __syncthreads();
    for (int s = 64; s > 0; s >>= 1) {
        if (t < s) red[t] = fmaxf(red[t], red[t + s]);
        __syncthreads();
    }
    float mx = red[0];

    const int nt   = f >> 3;
    const int lrow = f & 7;

    for (int k = t; k < KF; k += blockDim.x) {
        float hv = 0.0f;
        if (k < HALF_K) {
            double wj  = 0.54 - 0.46 * cos(2.0 * M_PI * (double)k / 250.0);
            double wjm = 0.54 - 0.46 * cos(2.0 * M_PI * (double)(250 - k) / 250.0);
            hv = (bp[HALF_K - 1 - k] / mx) * (float)(0.5 * (wj + wjm));
        } else if (k == HALF_K) {
            hv = 0.5f * (center / mx);           // s(125) = 2x -> halve tap
        }
        __half hh = __float2half_rn(hv);

        int ks = k >> 4, kk = k & 15;
        int bsel = kk >> 3;
        int q    = (kk >> 1) & 3;
        int e    = kk & 1;
        int lane = lrow * 4 + q;

        __half* dst = (__half*)&Hfrag_g[ks][nt][lane];
        dst[bsel * 2 + e] = hh;     // uint2 = 4 halves: b0.lo,b0.hi,b1.lo,b1.hi
    }
}

// ---------------------------------------------------------------------------
// Kernel 2: folded implicit-GEMM via mma.sync m16n8k16 fp16, single pass.
// CTA: 1 batch x 64 l x 80 f, 8 warps, 4 CTAs/SM (32 warps).
// Warp w = (mp = w&3, nh = w>>2): ONE m-tile mp, n-tiles [5nh, 5nh+5).
// Windows register-carried across the fully-unrolled kstep loop.
// Mirror: x[l0+r+250-k] = XR0[79 - r + k] with XR0[i] = x[l0+329-i].
// ---------------------------------------------------------------------------
__global__ void __launch_bounds__(THREADS, 4)
sinc_conv_kernel(const float* __restrict__ x, float* __restrict__ out)
{
    extern __shared__ __align__(16) Smem S[];
    float* xbuf = S->xbuf;

    const int b    = blockIdx.y;
    const int l0   = blockIdx.x * MTILE;
    const int tid  = threadIdx.x;
    const int w    = tid >> 5;
    const int lane = tid & 31;

    // ---- stage forward + reversed (and shifted) x copies, clamped ----
    {
        const float* xb = x + (size_t)b * L_IN;
        int i = tid;                       // window reads stay below 256
        int gf = l0 + i;
        xbuf[XF0 + i] = (gf < L_IN) ? xb[gf] : 0.0f;
        xbuf[XF1 + i] = (gf + 1 < L_IN) ? xb[gf + 1] : 0.0f;
        int gr = l0 + 329 - i;             // >= l0 + 74 >= 0
        xbuf[XR0 + i] = (gr < L_IN) ? xb[gr] : 0.0f;
        xbuf[XR1 + i] = (gr - 1 < L_IN) ? xb[gr - 1] : 0.0f;
    }
    __syncthreads();

    const int mp  = w & 3;
    const int nh  = w >> 2;
    const int gid = lane >> 2;      // 0..7
    const int tig = lane & 3;
    const int par = gid & 1;        // parity of r (16*mp even)
    const int qq  = 1 - par;        // parity of mirror index 79 - rA + k0

    const int rA  = 16 * mp + gid;  // row of this lane's m-tile

    const float2* Xf = (const float2*)(xbuf + (par ? XF1 : XF0));
    const float2* Xr = (const float2*)(xbuf + (qq ? XR1 : XR0));

    const int vb0 = (rA - par + 2 * tig) >> 1;        // fwd word, ks=0
    const int ub0 = (79 - rA + 2 * tig - qq) >> 1;    // rev word of (r, k0), ks=0

    float D[5][4];
    #pragma unroll
    for (int n = 0; n < 5; n++)
        #pragma unroll
        for (int e = 0; e < 4; e++)
            D[n][e] = 0.0f;

    // prologue window loads
    float2 F0 = Xf[vb0], F1 = Xf[vb0 + 4], F2 = Xf[vb0 + 8];
    float2 R0 = Xr[ub0 - 4], R1 = Xr[ub0], R2 = Xr[ub0 + 4];

    #pragma unroll
    for (int ks = 0; ks < KSTEPS; ks++) {
        uint4 Ah;
        Ah.x = mk_frag_hi(F0, R1);   // (r,   k0)
        Ah.y = mk_frag_hi(F1, R0);   // (r+8, k0)
        Ah.z = mk_frag_hi(F1, R2);   // (r,   k0+8)
        Ah.w = mk_frag_hi(F2, R1);   // (r+8, k0+8)

        const uint2* __restrict__ Hp = &Hfrag_g[ks][5 * nh][lane];
        #pragma unroll
        for (int n = 0; n < 5; n++) {
            uint2 Bf = Hp[n * 32];          // LDG.64, L1/L2-hot
            mma16816(D[n], Ah.x, Ah.y, Ah.z, Ah.w, Bf.x, Bf.y);
        }

        // slide windows by 8 f2-words (1 rename + 2 fresh LDS.64 per side)
        if (ks < KSTEPS - 1) {
            const int nb = 8 * (ks + 1);
            F0 = F2;
            F1 = Xf[vb0 + nb + 4];
            F2 = Xf[vb0 + nb + 8];
            R0 = R2;
            R1 = Xr[ub0 + nb];
            R2 = Xr[ub0 + nb + 4];
        }
    }

    // ---- store: l = l0 + 16*mp + rp (+8); f = 8(5nh+n) + 2q (+1) ----
    const int rp = lane >> 2;
    const int q  = lane & 3;
    const int l  = l0 + 16 * mp + rp;
    float* ob = out + (size_t)b * N_FILT * L_OUT;
    #pragma unroll
    for (int n = 0; n < 5; n++) {
        int f = (5 * nh + n) * 8 + q * 2;
        if (l < L_OUT) {
            ob[(size_t)f * L_OUT + l]       = D[n][0];
            ob[(size_t)(f + 1) * L_OUT + l] = D[n][1];
        }
        if (l + 8 < L_OUT) {
            ob[(size_t)f * L_OUT + l + 8]       = D[n][2];
            ob[(size_t)(f + 1) * L_OUT + l + 8] = D[n][3];
        }
    }
}

// ---------------------------------------------------------------------------
extern "C" void kernel_launch(void* const* d_in, const int* in_sizes, int n_in,
                              void* d_out, int out_size)
{
    const float* x       = (const float*)d_in[0];
    const float* norm_f1 = (const float*)d_in[1];
    const float* norm_f2 = (const float*)d_in[2];
    const float* ampl    = (const float*)d_in[3];
    float* out = (float*)d_out;

    cudaFuncSetAttribute(sinc_conv_kernel,
                         cudaFuncAttributeMaxDynamicSharedMemorySize,
                         (int)sizeof(Smem));

    build_filters_kernel<<<N_FILT, 128>>>(norm_f1, norm_f2, ampl);

    dim3 grid(NLT, BATCH);   // (497, 32)
    sinc_conv_kernel<<<grid, THREADS, sizeof(Smem)>>>(x, out);
}